// round 5
// baseline (speedup 1.0000x reference)
#include <cuda_runtime.h>
#include <cuda_bf16.h>
#include <math.h>

// Problem constants
#define BATCH 4
#define TSEQ  2048
#define CDIM  1024
#define NHEAD 16
#define HDIM  64
#define MROWS (BATCH * TSEQ)   // 8192

// Scratch (device globals: allocation-guard safe)
__device__ float g_q[MROWS * CDIM];
__device__ float g_k[MROWS * CDIM];
__device__ float g_v[MROWS * CDIM];
__device__ float g_ctx[MROWS * CDIM];

// ---------------------------------------------------------------------------
// SGEMM: C[M,N] = A[M,K] @ W[K,N] + bias[N]
// BM=BN=128, BK=16, 256 threads, 8x8 per thread.
// mode 0/1/2: write g_q/g_k/g_v with [B,H,T,D] scatter; A = x
// mode 3    : A = g_ctx, write outp row-major [M,N]
// ---------------------------------------------------------------------------
__global__ __launch_bounds__(256)
void sgemm_kernel(const float* __restrict__ A_in,
                  const float* __restrict__ W,
                  const float* __restrict__ bias,
                  float* __restrict__ outp,
                  int mode)
{
    const int M = MROWS, N = CDIM, K = CDIM;
    __shared__ float As[16][128];
    __shared__ float Bs[16][128];

    const float* A = (mode == 3) ? g_ctx : A_in;
    float* O;
    if      (mode == 0) O = g_q;
    else if (mode == 1) O = g_k;
    else if (mode == 2) O = g_v;
    else                O = outp;

    const int tid = threadIdx.x;
    const int tx = tid & 15;        // 0..15 -> 8 cols each
    const int ty = tid >> 4;        // 0..15 -> 8 rows each
    const int bx = blockIdx.x;      // N/128
    const int by = blockIdx.y;      // M/128

    // global load mapping
    const int aRow  = tid >> 2;     // 0..63 (+64)
    const int aCol4 = tid & 3;      // *4 -> col
    const int bRow  = tid >> 5;     // 0..7 (+8)
    const int bCol4 = tid & 31;     // *4 -> col

    const float* Aptr = A + (size_t)(by * 128) * K;
    const float* Wptr = W + bx * 128;

    float acc[8][8];
#pragma unroll
    for (int i = 0; i < 8; i++)
#pragma unroll
        for (int j = 0; j < 8; j++) acc[i][j] = 0.f;

    for (int k0 = 0; k0 < K; k0 += 16) {
        // load A tile (128x16), store transposed into As[k][m]
#pragma unroll
        for (int it = 0; it < 2; it++) {
            int r = aRow + it * 64;
            float4 v = *(const float4*)(Aptr + (size_t)r * K + k0 + aCol4 * 4);
            As[aCol4 * 4 + 0][r] = v.x;
            As[aCol4 * 4 + 1][r] = v.y;
            As[aCol4 * 4 + 2][r] = v.z;
            As[aCol4 * 4 + 3][r] = v.w;
        }
        // load B tile (16x128) row-major
#pragma unroll
        for (int it = 0; it < 2; it++) {
            int r = bRow + it * 8;
            float4 v = *(const float4*)(Wptr + (size_t)(k0 + r) * N + bCol4 * 4);
            *(float4*)&Bs[r][bCol4 * 4] = v;
        }
        __syncthreads();

#pragma unroll
        for (int kk = 0; kk < 16; kk++) {
            float ar[8], br[8];
            const float4* a4 = (const float4*)&As[kk][ty * 8];
            const float4* b4 = (const float4*)&Bs[kk][tx * 8];
            float4 av0 = a4[0], av1 = a4[1];
            float4 bv0 = b4[0], bv1 = b4[1];
            ar[0]=av0.x; ar[1]=av0.y; ar[2]=av0.z; ar[3]=av0.w;
            ar[4]=av1.x; ar[5]=av1.y; ar[6]=av1.z; ar[7]=av1.w;
            br[0]=bv0.x; br[1]=bv0.y; br[2]=bv0.z; br[3]=bv0.w;
            br[4]=bv1.x; br[5]=bv1.y; br[6]=bv1.z; br[7]=bv1.w;
#pragma unroll
            for (int i = 0; i < 8; i++)
#pragma unroll
                for (int j = 0; j < 8; j++)
                    acc[i][j] = fmaf(ar[i], br[j], acc[i][j]);
        }
        __syncthreads();
    }

    // epilogue: bias + store
    const int n0 = bx * 128 + tx * 8;
    float4 bb0 = *(const float4*)(bias + n0);
    float4 bb1 = *(const float4*)(bias + n0 + 4);

#pragma unroll
    for (int i = 0; i < 8; i++) {
        int m = by * 128 + ty * 8 + i;
        float4 r0, r1;
        r0.x = acc[i][0] + bb0.x; r0.y = acc[i][1] + bb0.y;
        r0.z = acc[i][2] + bb0.z; r0.w = acc[i][3] + bb0.w;
        r1.x = acc[i][4] + bb1.x; r1.y = acc[i][5] + bb1.y;
        r1.z = acc[i][6] + bb1.z; r1.w = acc[i][7] + bb1.w;
        size_t base;
        if (mode <= 2) {
            // scatter to [B,H,T,D]: b=m>>11, t=m&2047, h=n0>>6, d=n0&63
            int b = m >> 11, t = m & (TSEQ - 1);
            int h = n0 >> 6, d = n0 & (HDIM - 1);
            base = (((size_t)(b * NHEAD + h) * TSEQ + t) * HDIM) + d;
        } else {
            base = (size_t)m * N + n0;
        }
        *(float4*)(O + base)     = r0;
        *(float4*)(O + base + 4) = r1;
    }
}

// ---------------------------------------------------------------------------
// Causal attention, fp32, online softmax.
// Grid: (T/128, B*H). 128 threads, 1 query per thread.
// K/V tiles of 64 keys x 64 dim staged in smem.
// Writes context to g_ctx in [B,T,C] layout.
// ---------------------------------------------------------------------------
__global__ __launch_bounds__(128)
void attn_kernel()
{
    const int bh  = blockIdx.y;                       // b*16 + h
    const int qb  = (gridDim.x - 1) - blockIdx.x;     // largest-first for balance
    const int tid = threadIdx.x;
    const int qi  = qb * 128 + tid;
    const float scale = 0.125f;                       // 1/sqrt(64)

    __shared__ float4 Ks[64][16];
    __shared__ float4 Vs[64][16];

    const float4* qptr = (const float4*)(g_q + ((size_t)bh * TSEQ + qi) * HDIM);
    float4 qv[16], ov[16];
#pragma unroll
    for (int d = 0; d < 16; d++) {
        qv[d] = qptr[d];
        ov[d] = make_float4(0.f, 0.f, 0.f, 0.f);
    }
    float m = -1e30f, l = 0.f;

    const int ntiles = 2 * qb + 2;                    // covers keys 0..qb*128+127
    const float4* kbase = (const float4*)(g_k + (size_t)bh * TSEQ * HDIM);
    const float4* vbase = (const float4*)(g_v + (size_t)bh * TSEQ * HDIM);

    for (int t0 = 0; t0 < ntiles; t0++) {
        const int j0 = t0 * 64;
        const float4* kp = kbase + (size_t)j0 * 16;   // 64 rows x 16 float4
        const float4* vp = vbase + (size_t)j0 * 16;
#pragma unroll
        for (int it = 0; it < 8; it++) {
            int idx = tid + it * 128;                 // 0..1023
            ((float4*)Ks)[idx] = kp[idx];
            ((float4*)Vs)[idx] = vp[idx];
        }
        __syncthreads();

        int jmax = qi - j0 + 1;
        if (jmax > 64) jmax = 64;
        for (int j = 0; j < jmax; j++) {
            // s = scale * dot(q, k_j)  (4 parallel chains)
            float4 a = make_float4(0.f, 0.f, 0.f, 0.f);
#pragma unroll
            for (int d = 0; d < 16; d++) {
                float4 kv = Ks[j][d];
                a.x = fmaf(qv[d].x, kv.x, a.x);
                a.y = fmaf(qv[d].y, kv.y, a.y);
                a.z = fmaf(qv[d].z, kv.z, a.z);
                a.w = fmaf(qv[d].w, kv.w, a.w);
            }
            float s = ((a.x + a.y) + (a.z + a.w)) * scale;

            if (s > m) {
                float corr = __expf(m - s);
                m = s;
                l *= corr;
#pragma unroll
                for (int d = 0; d < 16; d++) {
                    ov[d].x *= corr; ov[d].y *= corr;
                    ov[d].z *= corr; ov[d].w *= corr;
                }
            }
            float p = __expf(s - m);
            l += p;
#pragma unroll
            for (int d = 0; d < 16; d++) {
                float4 vv = Vs[j][d];
                ov[d].x = fmaf(p, vv.x, ov[d].x);
                ov[d].y = fmaf(p, vv.y, ov[d].y);
                ov[d].z = fmaf(p, vv.z, ov[d].z);
                ov[d].w = fmaf(p, vv.w, ov[d].w);
            }
        }
        __syncthreads();
    }

    const float inv = 1.f / l;
    // ctx[b, t, h*64+d], b=bh>>4, h=bh&15, t=qi
    float4* obase = (float4*)(g_ctx
        + ((size_t)(bh >> 4) * TSEQ + qi) * CDIM + (bh & 15) * HDIM);
#pragma unroll
    for (int d = 0; d < 16; d++) {
        float4 o = ov[d];
        o.x *= inv; o.y *= inv; o.z *= inv; o.w *= inv;
        obase[d] = o;
    }
}

// ---------------------------------------------------------------------------
// kernel_launch: 5 graph-capturable launches, no allocation, no sync.
// Inputs: x, Wq, bq, Wk, bk, Wv, bv, Wo, bo
// ---------------------------------------------------------------------------
extern "C" void kernel_launch(void* const* d_in, const int* in_sizes, int n_in,
                              void* d_out, int out_size)
{
    const float* x  = (const float*)d_in[0];
    const float* Wq = (const float*)d_in[1];
    const float* bq = (const float*)d_in[2];
    const float* Wk = (const float*)d_in[3];
    const float* bk = (const float*)d_in[4];
    const float* Wv = (const float*)d_in[5];
    const float* bv = (const float*)d_in[6];
    const float* Wo = (const float*)d_in[7];
    const float* bo = (const float*)d_in[8];
    float* out = (float*)d_out;

    dim3 ggrid(CDIM / 128, MROWS / 128);   // (8, 64)
    dim3 gblock(256);

    sgemm_kernel<<<ggrid, gblock>>>(x, Wq, bq, nullptr, 0);
    sgemm_kernel<<<ggrid, gblock>>>(x, Wk, bk, nullptr, 1);
    sgemm_kernel<<<ggrid, gblock>>>(x, Wv, bv, nullptr, 2);

    dim3 agrid(TSEQ / 128, BATCH * NHEAD); // (16, 64)
    attn_kernel<<<agrid, 128>>>();

    sgemm_kernel<<<ggrid, gblock>>>(nullptr, Wo, bo, out, 3);
}

// round 7
// speedup vs baseline: 1.5927x; 1.5927x over previous
#include <cuda_runtime.h>
#include <math.h>
#include <stdint.h>

// Problem constants
#define BATCH 4
#define TSEQ  2048
#define CDIM  1024
#define NHEAD 16
#define HDIM  64
#define MROWS (BATCH * TSEQ)   // 8192

// Scratch (device globals: allocation-guard safe)
__device__ float g_q[MROWS * CDIM];
__device__ float g_k[MROWS * CDIM];
__device__ float g_v[MROWS * CDIM];
__device__ float g_ctx[MROWS * CDIM];
__device__ float g_wt[4 * CDIM * CDIM];   // transposed tf32 weights [n][k]

__device__ __forceinline__ uint32_t f32_to_tf32(float x) {
    uint32_t u;
    asm("cvt.rna.tf32.f32 %0, %1;" : "=r"(u) : "f"(x));
    return u;
}

// ---------------------------------------------------------------------------
// Weight transpose + tf32 round: g_wt[mat][n][k] = tf32(W[mat][k][n])
// ---------------------------------------------------------------------------
__global__ void transpose_w(const float* __restrict__ W0, const float* __restrict__ W1,
                            const float* __restrict__ W2, const float* __restrict__ W3)
{
    __shared__ float t[32][33];
    const int z = blockIdx.z;
    const float* W = (z == 0) ? W0 : (z == 1) ? W1 : (z == 2) ? W2 : W3;
    float* o = g_wt + (size_t)z * CDIM * CDIM;
    const int k0 = blockIdx.x * 32, n0 = blockIdx.y * 32;
    const int tx = threadIdx.x, ty = threadIdx.y;   // 32 x 8
#pragma unroll
    for (int i = 0; i < 32; i += 8)
        t[ty + i][tx] = W[(size_t)(k0 + ty + i) * CDIM + n0 + tx];
    __syncthreads();
#pragma unroll
    for (int i = 0; i < 32; i += 8) {
        uint32_t u = f32_to_tf32(t[tx][ty + i]);
        o[(size_t)(n0 + ty + i) * CDIM + k0 + tx] = __uint_as_float(u);
    }
}

// ---------------------------------------------------------------------------
// tf32 mma.sync GEMM: C[M,N] = A[M,K] @ W[K,N] + bias
// BM=BN=128, BK=32, 256 threads (8 warps, each a 32x64 warp tile).
// A row-major tf32 in smem [128][36]; B (= Wt[n][k]) col-major tf32 [128][36].
// mode 0: A = x, Wt/bias/out selected by blockIdx.z (q/k/v), scatter [B,H,T,D]
// mode 1: A = g_ctx, Wt = g_wt[3], bias=bo, out row-major (d_out)
// ---------------------------------------------------------------------------
#define BK 32
#define NCHUNK (CDIM / BK)          // 32
#define TSTRIDE 36                  // padded floats per row
#define TILE_F (128 * TSTRIDE)      // floats per tile buffer
#define SMEM_DYN (4 * TILE_F * 4)   // 2 stages x (A+B) = 73728 B

__device__ __forceinline__ void mma_tf32(float* c, const uint32_t* a, const uint32_t* b) {
    asm volatile(
        "mma.sync.aligned.m16n8k8.row.col.f32.tf32.tf32.f32 "
        "{%0,%1,%2,%3}, {%4,%5,%6,%7}, {%8,%9}, {%0,%1,%2,%3};"
        : "+f"(c[0]), "+f"(c[1]), "+f"(c[2]), "+f"(c[3])
        : "r"(a[0]), "r"(a[1]), "r"(a[2]), "r"(a[3]), "r"(b[0]), "r"(b[1]));
}

__global__ __launch_bounds__(256)
void gemm_tf32(const float* __restrict__ Ain,
               const float* __restrict__ bq, const float* __restrict__ bk,
               const float* __restrict__ bv,
               float* __restrict__ outp, int mode)
{
    extern __shared__ float sm[];

    const int tid = threadIdx.x;
    const int wid = tid >> 5, lane = tid & 31;
    const int bx = blockIdx.x, by = blockIdx.y, bz = blockIdx.z;

    const float* A;
    const float* Wt;
    const float* bias;
    float* O;
    if (mode == 0) {
        A = Ain;
        Wt = g_wt + (size_t)bz * CDIM * CDIM;
        bias = (bz == 0) ? bq : (bz == 1) ? bk : bv;
        O = (bz == 0) ? g_q : (bz == 1) ? g_k : g_v;
    } else {
        A = g_ctx;
        Wt = g_wt + (size_t)3 * CDIM * CDIM;
        bias = bq;
        O = outp;
    }

    const float* Abase = A  + (size_t)(by * 128) * CDIM;
    const float* Bbase = Wt + (size_t)(bx * 128) * CDIM;

    // load mapping: 1024 float4 per matrix tile, 4 per thread
    const int lr  = tid >> 1;          // 0..127 row (2 threads/row)? no:
    (void)lr;
    // e = tid + i*256, r = e>>3 (0..127), c4 = e&7 (float4 col)

    float4 pa[4], pb[4];
    auto ldg_tile = [&](int c) {
        const float* Ag = Abase + c * BK;
        const float* Bg = Bbase + c * BK;
#pragma unroll
        for (int i = 0; i < 4; i++) {
            int e = tid + i * 256;
            int r = e >> 3, c4 = e & 7;
            pa[i] = *(const float4*)(Ag + (size_t)r * CDIM + c4 * 4);
            pb[i] = *(const float4*)(Bg + (size_t)r * CDIM + c4 * 4);
        }
    };
    auto sts_tile = [&](int s) {
        float* As = sm + (size_t)s * TILE_F;
        float* Bs = sm + (size_t)(2 + s) * TILE_F;
#pragma unroll
        for (int i = 0; i < 4; i++) {
            int e = tid + i * 256;
            int r = e >> 3, c4 = e & 7;
            float* ap = As + r * TSTRIDE + c4 * 4;
            ap[0] = __uint_as_float(f32_to_tf32(pa[i].x));
            ap[1] = __uint_as_float(f32_to_tf32(pa[i].y));
            ap[2] = __uint_as_float(f32_to_tf32(pa[i].z));
            ap[3] = __uint_as_float(f32_to_tf32(pa[i].w));
            float* bp = Bs + r * TSTRIDE + c4 * 4;
            bp[0] = pb[i].x; bp[1] = pb[i].y; bp[2] = pb[i].z; bp[3] = pb[i].w;
        }
    };

    // warp tile: 32 (M) x 64 (N)
    const int m0w = (wid >> 1) * 32;
    const int n0w = (wid & 1) * 64;
    const int lq = lane >> 2;          // 0..7
    const int lr4 = lane & 3;          // 0..3

    float acc[2][8][4];
#pragma unroll
    for (int mi = 0; mi < 2; mi++)
#pragma unroll
        for (int ni = 0; ni < 8; ni++)
#pragma unroll
            for (int j = 0; j < 4; j++) acc[mi][ni][j] = 0.f;

    ldg_tile(0);
    sts_tile(0);
    __syncthreads();

    for (int c = 0; c < NCHUNK; c++) {
        if (c + 1 < NCHUNK) ldg_tile(c + 1);

        const uint32_t* As = (const uint32_t*)(sm + (size_t)(c & 1) * TILE_F);
        const uint32_t* Bs = (const uint32_t*)(sm + (size_t)(2 + (c & 1)) * TILE_F);

#pragma unroll
        for (int kk = 0; kk < BK; kk += 8) {
            uint32_t af[2][4], bf[8][2];
#pragma unroll
            for (int mi = 0; mi < 2; mi++) {
                int row = m0w + mi * 16 + lq;
                af[mi][0] = As[row * TSTRIDE + kk + lr4];
                af[mi][1] = As[(row + 8) * TSTRIDE + kk + lr4];
                af[mi][2] = As[row * TSTRIDE + kk + 4 + lr4];
                af[mi][3] = As[(row + 8) * TSTRIDE + kk + 4 + lr4];
            }
#pragma unroll
            for (int ni = 0; ni < 8; ni++) {
                int col = n0w + ni * 8 + lq;
                bf[ni][0] = Bs[col * TSTRIDE + kk + lr4];
                bf[ni][1] = Bs[col * TSTRIDE + kk + 4 + lr4];
            }
#pragma unroll
            for (int mi = 0; mi < 2; mi++)
#pragma unroll
                for (int ni = 0; ni < 8; ni++)
                    mma_tf32(acc[mi][ni], af[mi], bf[ni]);
        }

        if (c + 1 < NCHUNK) {
            sts_tile((c + 1) & 1);
            __syncthreads();
        }
    }

    // Epilogue: bias + store (float2 per fragment row)
#pragma unroll
    for (int mi = 0; mi < 2; mi++) {
#pragma unroll
        for (int ni = 0; ni < 8; ni++) {
            int n = bx * 128 + n0w + ni * 8 + 2 * lr4;
            float bx0 = __ldg(&bias[n]), bx1 = __ldg(&bias[n + 1]);
            int m = by * 128 + m0w + mi * 16 + lq;
            float2 v0 = make_float2(acc[mi][ni][0] + bx0, acc[mi][ni][1] + bx1);
            float2 v1 = make_float2(acc[mi][ni][2] + bx0, acc[mi][ni][3] + bx1);
            size_t g0, g1;
            if (mode == 0) {
                int h = n >> 6, d = n & (HDIM - 1);
                int b0 = m >> 11, t0 = m & (TSEQ - 1);
                int b1 = (m + 8) >> 11, t1 = (m + 8) & (TSEQ - 1);
                g0 = (((size_t)(b0 * NHEAD + h) * TSEQ + t0) * HDIM) + d;
                g1 = (((size_t)(b1 * NHEAD + h) * TSEQ + t1) * HDIM) + d;
            } else {
                g0 = (size_t)m * CDIM + n;
                g1 = (size_t)(m + 8) * CDIM + n;
            }
            *(float2*)(O + g0) = v0;
            *(float2*)(O + g1) = v1;
        }
    }
}

// ---------------------------------------------------------------------------
// Causal attention, fp32, online softmax (unchanged — passed round 4).
// ---------------------------------------------------------------------------
__global__ __launch_bounds__(128)
void attn_kernel()
{
    const int bh  = blockIdx.y;
    const int qb  = (gridDim.x - 1) - blockIdx.x;
    const int tid = threadIdx.x;
    const int qi  = qb * 128 + tid;
    const float scale = 0.125f;

    __shared__ float4 Ks[64][16];
    __shared__ float4 Vs[64][16];

    const float4* qptr = (const float4*)(g_q + ((size_t)bh * TSEQ + qi) * HDIM);
    float4 qv[16], ov[16];
#pragma unroll
    for (int d = 0; d < 16; d++) {
        qv[d] = qptr[d];
        ov[d] = make_float4(0.f, 0.f, 0.f, 0.f);
    }
    float m = -1e30f, l = 0.f;

    const int ntiles = 2 * qb + 2;
    const float4* kbase = (const float4*)(g_k + (size_t)bh * TSEQ * HDIM);
    const float4* vbase = (const float4*)(g_v + (size_t)bh * TSEQ * HDIM);

    for (int t0 = 0; t0 < ntiles; t0++) {
        const int j0 = t0 * 64;
        const float4* kp = kbase + (size_t)j0 * 16;
        const float4* vp = vbase + (size_t)j0 * 16;
#pragma unroll
        for (int it = 0; it < 8; it++) {
            int idx = tid + it * 128;
            ((float4*)Ks)[idx] = kp[idx];
            ((float4*)Vs)[idx] = vp[idx];
        }
        __syncthreads();

        int jmax = qi - j0 + 1;
        if (jmax > 64) jmax = 64;
        for (int j = 0; j < jmax; j++) {
            float4 a = make_float4(0.f, 0.f, 0.f, 0.f);
#pragma unroll
            for (int d = 0; d < 16; d++) {
                float4 kv = Ks[j][d];
                a.x = fmaf(qv[d].x, kv.x, a.x);
                a.y = fmaf(qv[d].y, kv.y, a.y);
                a.z = fmaf(qv[d].z, kv.z, a.z);
                a.w = fmaf(qv[d].w, kv.w, a.w);
            }
            float s = ((a.x + a.y) + (a.z + a.w)) * scale;

            if (s > m) {
                float corr = __expf(m - s);
                m = s;
                l *= corr;
#pragma unroll
                for (int d = 0; d < 16; d++) {
                    ov[d].x *= corr; ov[d].y *= corr;
                    ov[d].z *= corr; ov[d].w *= corr;
                }
            }
            float p = __expf(s - m);
            l += p;
#pragma unroll
            for (int d = 0; d < 16; d++) {
                float4 vv = Vs[j][d];
                ov[d].x = fmaf(p, vv.x, ov[d].x);
                ov[d].y = fmaf(p, vv.y, ov[d].y);
                ov[d].z = fmaf(p, vv.z, ov[d].z);
                ov[d].w = fmaf(p, vv.w, ov[d].w);
            }
        }
        __syncthreads();
    }

    const float inv = 1.f / l;
    float4* obase = (float4*)(g_ctx
        + ((size_t)(bh >> 4) * TSEQ + qi) * CDIM + (bh & 15) * HDIM);
#pragma unroll
    for (int d = 0; d < 16; d++) {
        float4 o = ov[d];
        o.x *= inv; o.y *= inv; o.z *= inv; o.w *= inv;
        obase[d] = o;
    }
}

// ---------------------------------------------------------------------------
// kernel_launch: transpose -> QKV GEMM (fused) -> attention -> O GEMM
// ---------------------------------------------------------------------------
extern "C" void kernel_launch(void* const* d_in, const int* in_sizes, int n_in,
                              void* d_out, int out_size)
{
    const float* x  = (const float*)d_in[0];
    const float* Wq = (const float*)d_in[1];
    const float* bq = (const float*)d_in[2];
    const float* Wk = (const float*)d_in[3];
    const float* bk = (const float*)d_in[4];
    const float* Wv = (const float*)d_in[5];
    const float* bv = (const float*)d_in[6];
    const float* Wo = (const float*)d_in[7];
    const float* bo = (const float*)d_in[8];
    float* out = (float*)d_out;

    cudaFuncSetAttribute(gemm_tf32, cudaFuncAttributeMaxDynamicSharedMemorySize, SMEM_DYN);

    dim3 tgrid(CDIM / 32, CDIM / 32, 4);
    transpose_w<<<tgrid, dim3(32, 8)>>>(Wq, Wk, Wv, Wo);

    dim3 qkv_grid(CDIM / 128, MROWS / 128, 3);   // (8, 64, 3)
    gemm_tf32<<<qkv_grid, 256, SMEM_DYN>>>(x, bq, bk, bv, nullptr, 0);

    dim3 agrid(TSEQ / 128, BATCH * NHEAD);       // (16, 64)
    attn_kernel<<<agrid, 128>>>();

    dim3 o_grid(CDIM / 128, MROWS / 128, 1);     // (8, 64)
    gemm_tf32<<<o_grid, 256, SMEM_DYN>>>(nullptr, bo, nullptr, nullptr, out, 1);
}